// round 2
// baseline (speedup 1.0000x reference)
#include <cuda_runtime.h>
#include <cuda_bf16.h>
#include <cstdint>

#define D 128
#define GN_EPS 1e-5f
#define MAXN 50000
#define MAXE 800000

// ---------------- scratch ----------------
__device__ float g_t[(size_t)MAXN * D];   // GEMM output, pre-scaled by dinv[row]
__device__ float g_h[(size_t)MAXN * D];   // aggregated layer output
__device__ int   g_cnt[MAXN];             // in-degree (excluding self loop)
__device__ float g_dinv[MAXN];
__device__ int   g_rowp[MAXN];            // CSR row start
__device__ int   g_cur[MAXN];             // fill cursor
__device__ int   g_csr[MAXE];             // src ids grouped by dst
__device__ float g_cs[D];
__device__ float g_css[D];
__device__ float g_scale[D];
__device__ float g_shift[D];

// ---------------- degree / CSR build ----------------
__global__ void zero_cnt_k(int n) {
    int i = blockIdx.x * blockDim.x + threadIdx.x;
    if (i < n) g_cnt[i] = 0;
    if (blockIdx.x == 0 && threadIdx.x < D) {
        g_cs[threadIdx.x] = 0.0f;
        g_css[threadIdx.x] = 0.0f;
    }
}

__global__ void hist_k(const int* __restrict__ dst, int e) {
    int i = blockIdx.x * blockDim.x + threadIdx.x;
    if (i < e) atomicAdd(&g_cnt[dst[i]], 1);
}

__global__ void dinv_k(int n) {
    int i = blockIdx.x * blockDim.x + threadIdx.x;
    if (i < n) g_dinv[i] = rsqrtf((float)g_cnt[i] + 1.0f);
}

// single-block exclusive scan over g_cnt -> g_rowp, g_cur
__global__ void scan_k(int n) {
    __shared__ int sh[1024];
    __shared__ int run;
    if (threadIdx.x == 0) run = 0;
    __syncthreads();
    for (int base = 0; base < n; base += 1024) {
        int i = base + threadIdx.x;
        int v = (i < n) ? g_cnt[i] : 0;
        sh[threadIdx.x] = v;
        __syncthreads();
#pragma unroll
        for (int off = 1; off < 1024; off <<= 1) {
            int t = (threadIdx.x >= off) ? sh[threadIdx.x - off] : 0;
            __syncthreads();
            sh[threadIdx.x] += t;
            __syncthreads();
        }
        int excl = sh[threadIdx.x] - v;
        if (i < n) {
            g_rowp[i] = run + excl;
            g_cur[i]  = run + excl;
        }
        __syncthreads();
        if (threadIdx.x == 0) run += sh[1023];
        __syncthreads();
    }
}

__global__ void fill_k(const int* __restrict__ src, const int* __restrict__ dst, int e) {
    int i = blockIdx.x * blockDim.x + threadIdx.x;
    if (i < e) {
        int pos = atomicAdd(&g_cur[dst[i]], 1);
        g_csr[pos] = src[i];
    }
}

// ---------------- SGEMM: [M,128] @ [128,128] -> g_t (scaled by dinv) ----------
// A == nullptr: read g_h, applying norm scale/shift + relu on load.
#define BM 64
#define BK 32
__global__ void __launch_bounds__(256) gemm_k(const float* __restrict__ A,
                                              const float* __restrict__ W,
                                              int M, int transform) {
    __shared__ float xs[BM][BK + 1];
    __shared__ float ws[BK][D];
    __shared__ float s_sc[D], s_sh[D];
    const float* __restrict__ a_ptr = A ? A : g_h;

    int tid  = threadIdx.x;
    int tcol = tid & 31;
    int trow = tid >> 5;
    int row0 = blockIdx.x * BM;

    if (transform && tid < D) {
        s_sc[tid] = g_scale[tid];
        s_sh[tid] = g_shift[tid];
    }
    if (transform) __syncthreads();

    float acc[8][4];
#pragma unroll
    for (int i = 0; i < 8; i++)
#pragma unroll
        for (int j = 0; j < 4; j++) acc[i][j] = 0.0f;

    for (int kk = 0; kk < D; kk += BK) {
#pragma unroll
        for (int i = 0; i < 8; i++) {
            int idx = tid + i * 256;
            int r = idx >> 5, k = idx & 31;
            int gr = row0 + r;
            float v = (gr < M) ? a_ptr[(size_t)gr * D + kk + k] : 0.0f;
            if (transform) v = fmaxf(fmaf(v, s_sc[kk + k], s_sh[kk + k]), 0.0f);
            xs[r][k] = v;
        }
#pragma unroll
        for (int i = 0; i < 16; i++) {
            int idx = tid + i * 256;
            int k = idx >> 7, c = idx & 127;
            ws[k][c] = W[(size_t)(kk + k) * D + c];
        }
        __syncthreads();
#pragma unroll
        for (int k = 0; k < BK; k++) {
            float4 wv = *(const float4*)&ws[k][tcol * 4];
#pragma unroll
            for (int i = 0; i < 8; i++) {
                float a = xs[trow * 8 + i][k];
                acc[i][0] += a * wv.x;
                acc[i][1] += a * wv.y;
                acc[i][2] += a * wv.z;
                acc[i][3] += a * wv.w;
            }
        }
        __syncthreads();
    }
#pragma unroll
    for (int i = 0; i < 8; i++) {
        int gr = row0 + trow * 8 + i;
        if (gr < M) {
            float di = g_dinv[gr];
            float4 o = make_float4(acc[i][0] * di, acc[i][1] * di,
                                   acc[i][2] * di, acc[i][3] * di);
            *(float4*)&g_t[(size_t)gr * D + tcol * 4] = o;
        }
    }
}

// ---------------- CSR gather aggregation ----------------
// MODE 0: write g_h, accumulate GraphNorm stats.
// MODE 1: fuse output head (h @ Wout + bout) -> out, no g_h write.
template <int MODE>
__global__ void __launch_bounds__(256) gather_k(const float* __restrict__ b,
                                                const float* __restrict__ Wout,
                                                const float* __restrict__ bout,
                                                float* __restrict__ out, int n) {
    int lane = threadIdx.x & 31;
    int warp = (blockIdx.x * blockDim.x + threadIdx.x) >> 5;
    int nwarps = (gridDim.x * blockDim.x) >> 5;

    float4 bb = *(const float4*)&b[lane * 4];
    float4 ssum = make_float4(0, 0, 0, 0);
    float4 ssq  = make_float4(0, 0, 0, 0);
    float w0[4], w1[4];
    float bo0 = 0.0f, bo1 = 0.0f;
    if (MODE == 1) {
#pragma unroll
        for (int j = 0; j < 4; j++) {
            w0[j] = __ldg(&Wout[(lane * 4 + j) * 2 + 0]);
            w1[j] = __ldg(&Wout[(lane * 4 + j) * 2 + 1]);
        }
        bo0 = __ldg(&bout[0]);
        bo1 = __ldg(&bout[1]);
    }

    for (int d = warp; d < n; d += nwarps) {
        float4 acc = *(const float4*)&g_t[(size_t)d * D + lane * 4];  // self loop (pre-scaled)
        int beg = g_rowp[d];
        int end = beg + g_cnt[d];
        int e = beg;
        for (; e + 4 <= end; e += 4) {
            int s0 = g_csr[e], s1 = g_csr[e + 1], s2 = g_csr[e + 2], s3 = g_csr[e + 3];
            float4 v0 = *(const float4*)&g_t[(size_t)s0 * D + lane * 4];
            float4 v1 = *(const float4*)&g_t[(size_t)s1 * D + lane * 4];
            float4 v2 = *(const float4*)&g_t[(size_t)s2 * D + lane * 4];
            float4 v3 = *(const float4*)&g_t[(size_t)s3 * D + lane * 4];
            acc.x += (v0.x + v1.x) + (v2.x + v3.x);
            acc.y += (v0.y + v1.y) + (v2.y + v3.y);
            acc.z += (v0.z + v1.z) + (v2.z + v3.z);
            acc.w += (v0.w + v1.w) + (v2.w + v3.w);
        }
        for (; e < end; e++) {
            int s = g_csr[e];
            float4 v = *(const float4*)&g_t[(size_t)s * D + lane * 4];
            acc.x += v.x; acc.y += v.y; acc.z += v.z; acc.w += v.w;
        }
        float di = g_dinv[d];
        acc.x = fmaf(acc.x, di, bb.x);
        acc.y = fmaf(acc.y, di, bb.y);
        acc.z = fmaf(acc.z, di, bb.z);
        acc.w = fmaf(acc.w, di, bb.w);

        if (MODE == 0) {
            *(float4*)&g_h[(size_t)d * D + lane * 4] = acc;
            ssum.x += acc.x; ssum.y += acc.y; ssum.z += acc.z; ssum.w += acc.w;
            ssq.x += acc.x * acc.x; ssq.y += acc.y * acc.y;
            ssq.z += acc.z * acc.z; ssq.w += acc.w * acc.w;
        } else {
            float a0 = acc.x * w0[0] + acc.y * w0[1] + acc.z * w0[2] + acc.w * w0[3];
            float a1 = acc.x * w1[0] + acc.y * w1[1] + acc.z * w1[2] + acc.w * w1[3];
#pragma unroll
            for (int off = 16; off > 0; off >>= 1) {
                a0 += __shfl_down_sync(0xFFFFFFFFu, a0, off);
                a1 += __shfl_down_sync(0xFFFFFFFFu, a1, off);
            }
            if (lane == 0) {
                out[(size_t)d * 2 + 0] = a0 + bo0;
                out[(size_t)d * 2 + 1] = a1 + bo1;
            }
        }
    }

    if (MODE == 0) {
        atomicAdd(&g_cs[lane * 4 + 0], ssum.x);
        atomicAdd(&g_cs[lane * 4 + 1], ssum.y);
        atomicAdd(&g_cs[lane * 4 + 2], ssum.z);
        atomicAdd(&g_cs[lane * 4 + 3], ssum.w);
        atomicAdd(&g_css[lane * 4 + 0], ssq.x);
        atomicAdd(&g_css[lane * 4 + 1], ssq.y);
        atomicAdd(&g_css[lane * 4 + 2], ssq.z);
        atomicAdd(&g_css[lane * 4 + 3], ssq.w);
    }
}

// ---------------- GraphNorm finalize (also re-zeroes stats) ----------------
__global__ void finalize_k(const float* __restrict__ w, const float* __restrict__ b,
                           const float* __restrict__ a, int n) {
    int c = threadIdx.x;
    float inv_n = 1.0f / (float)n;
    float m = g_cs[c] * inv_n;
    float msq = g_css[c] * inv_n;
    float al = a[c];
    float var = msq - (2.0f * al - al * al) * m * m;
    float sc = rsqrtf(var + GN_EPS) * w[c];
    g_scale[c] = sc;
    g_shift[c] = b[c] - al * m * sc;
    g_cs[c] = 0.0f;
    g_css[c] = 0.0f;
}

// ---------------- launch ----------------
extern "C" void kernel_launch(void* const* d_in, const int* in_sizes, int n_in,
                              void* d_out, int out_size) {
    const float* x    = (const float*)d_in[0];
    const int*   ei   = (const int*)d_in[1];
    const float* W1   = (const float*)d_in[2];
    const float* b1   = (const float*)d_in[3];
    const float* W2   = (const float*)d_in[4];
    const float* b2   = (const float*)d_in[5];
    const float* W3   = (const float*)d_in[6];
    const float* b3   = (const float*)d_in[7];
    const float* gn1w = (const float*)d_in[8];
    const float* gn1b = (const float*)d_in[9];
    const float* gn1a = (const float*)d_in[10];
    const float* gn2w = (const float*)d_in[11];
    const float* gn2b = (const float*)d_in[12];
    const float* gn2a = (const float*)d_in[13];
    const float* Wout = (const float*)d_in[14];
    const float* bout = (const float*)d_in[15];

    int n = in_sizes[0] / D;
    int e = in_sizes[1] / 2;
    const int* src = ei;
    const int* dst = ei + e;

    int node_blocks = (n + 255) / 256;
    int edge_blocks = (e + 255) / 256;
    int gemm_blocks = (n + BM - 1) / BM;
    int gather_blocks = 2 * 148;   // grid-stride, ~16 warps/SM

    // CSR + degree build (once per launch, reused by all 3 layers)
    zero_cnt_k<<<node_blocks, 256>>>(n);
    hist_k<<<edge_blocks, 256>>>(dst, e);
    dinv_k<<<node_blocks, 256>>>(n);
    scan_k<<<1, 1024>>>(n);
    fill_k<<<edge_blocks, 256>>>(src, dst, e);

    // ---- layer 1 ----
    gemm_k<<<gemm_blocks, 256>>>(x, W1, n, 0);
    gather_k<0><<<gather_blocks, 256>>>(b1, nullptr, nullptr, nullptr, n);
    finalize_k<<<1, 128>>>(gn1w, gn1b, gn1a, n);

    // ---- layer 2 ----
    gemm_k<<<gemm_blocks, 256>>>(nullptr, W2, n, 1);
    gather_k<0><<<gather_blocks, 256>>>(b2, nullptr, nullptr, nullptr, n);
    finalize_k<<<1, 128>>>(gn2w, gn2b, gn2a, n);

    // ---- layer 3 ----
    gemm_k<<<gemm_blocks, 256>>>(nullptr, W3, n, 1);
    gather_k<1><<<gather_blocks, 256>>>(b3, Wout, bout, (float*)d_out, n);
}